// round 13
// baseline (speedup 1.0000x reference)
#include <cuda_runtime.h>
#include <cuda_fp16.h>
#include <cstdint>

// ============================================================================
// Single-term fp16 mma.sync implicit-GEMM conv, round 13.
// Same math as R12 (D = ah*bh, A=w*64 fp16, B=x fp16, rel_err ~2.9e-4).
// NEW: A operand bypasses smem -- prep_a emits A in per-lane mma-fragment
// order; consumer warps load fragments directly via 256-bit
// ld.global.nc.L2::evict_last.v8.b32 (A is 2.4MB, pinned L2-resident).
// Removes cp.async + A-smem + A-ldsm (320 -> 256 L1 wavefronts/CTA/chunk).
// B path and epilogue identical to the R12/R8 champion.
// ============================================================================

#define KTOT   2304
#define KCH    72            // 2304 / 32
#define NPIMG  2916
#define OUTIMG (512*NPIMG)
#define XIMG   (256*3136)

#define STAGE_BYTES 8192     // B tile only
#define OFF_KOFF    16384                  // after 2 B stages
#define SMEM_BYTES  (OFF_KOFF + KTOT*4)    // 25600

// A (scaled x64, fp16) in mma-fragment order:
//   [mt(4)][ch(72)][wm(2)][kb(2)][lane(32)][am(4)][16B]
__device__ __align__(128) unsigned char g_afrag[4ull*72*8192];    // 2.4MB
// x as fp16
__device__ __align__(16) __half g_xh[32 * 256 * 56 * 56];         // 51.4MB

// ---------------------------------------------------------------------------
__device__ __forceinline__ uint32_t smem_u32(const void* p) {
    uint32_t a;
    asm("{ .reg .u64 t; cvta.to.shared.u64 t, %1; cvt.u32.u64 %0, t; }"
        : "=r"(a) : "l"(p));
    return a;
}
__device__ __forceinline__ void sts64(uint32_t addr, uint32_t a, uint32_t b) {
    asm volatile("st.shared.v2.b32 [%0], {%1, %2};" :: "r"(addr), "r"(a), "r"(b));
}
__device__ __forceinline__ void ldsm4(uint32_t a, uint32_t& r0, uint32_t& r1,
                                      uint32_t& r2, uint32_t& r3) {
    asm volatile("ldmatrix.sync.aligned.m8n8.x4.shared.b16 {%0,%1,%2,%3}, [%4];"
                 : "=r"(r0), "=r"(r1), "=r"(r2), "=r"(r3) : "r"(a));
}
__device__ __forceinline__ void mma_f16(float* c, const uint32_t* a,
                                        uint32_t b0, uint32_t b1) {
    asm volatile(
        "mma.sync.aligned.m16n8k16.row.col.f32.f16.f16.f32 "
        "{%0,%1,%2,%3}, {%4,%5,%6,%7}, {%8,%9}, {%0,%1,%2,%3};"
        : "+f"(c[0]), "+f"(c[1]), "+f"(c[2]), "+f"(c[3])
        : "r"(a[0]), "r"(a[1]), "r"(a[2]), "r"(a[3]), "r"(b0), "r"(b1));
}
// 256-bit A-fragment load, pinned in L2
__device__ __forceinline__ void ldg_a8(uint32_t* a, const void* p) {
    asm volatile(
        "ld.global.nc.L2::evict_last.v8.b32 {%0,%1,%2,%3,%4,%5,%6,%7}, [%8];"
        : "=r"(a[0]), "=r"(a[1]), "=r"(a[2]), "=r"(a[3]),
          "=r"(a[4]), "=r"(a[5]), "=r"(a[6]), "=r"(a[7])
        : "l"(p));
}
// B gather load: read-only path
__device__ __forceinline__ uint16_t ldg_b(const __half* p) {
    uint16_t v;
    asm volatile("ld.global.nc.u16 %0, [%1];" : "=h"(v) : "l"(p));
    return v;
}
// streaming output store (evict-first; don't evict g_xh / g_afrag from L2)
__device__ __forceinline__ void stg_cs2(float* p, float a, float b) {
    asm volatile("st.global.cs.v2.f32 [%0], {%1, %2};"
                 :: "l"(p), "f"(a), "f"(b) : "memory");
}
__device__ __forceinline__ uint32_t pack_h2(float a, float b) {
    __half ha = __float2half_rn(a), hb = __float2half_rn(b);
    return (uint32_t)*(uint16_t*)&ha | ((uint32_t)*(uint16_t*)&hb << 16);
}

// ---------------------------------------------------------------------------
// fused prep: blocks [0,25088) pack x -> fp16; [25088,25664) A -> fragments
// ---------------------------------------------------------------------------
__global__ void prep_all(const float* __restrict__ x, const float* __restrict__ w) {
    const int b = blockIdx.x;
    if (b < 25088) {
        int i = b * 256 + threadIdx.x;               // 6422528 total
        float4 v = ((const float4*)x)[i];
        uint32_t w0 = pack_h2(v.x, v.y);
        uint32_t w1 = pack_h2(v.z, v.w);
        ((uint2*)g_xh)[i] = make_uint2(w0, w1);
    } else {
        int i = (b - 25088) * 256 + threadIdx.x;     // 147456 total (16B each)
        int am   = i & 3;
        int lane = (i >> 2) & 31;
        int kb   = (i >> 7) & 1;
        int wm   = (i >> 8) & 1;
        int rest = i >> 9;                           // 0..287
        int ch = rest % 72, mt = rest / 72;
        int r  = lane >> 2;                          // 0..7
        int kk = (lane & 3) * 2;                     // 0,2,4,6
        int co = mt * 128 + wm * 64 + am * 16 + r;
        int k  = ch * 32 + kb * 16 + kk;
        const float* wp = w + (size_t)co * KTOT + k;
        float2 v00 = *(const float2*)(wp);                 // A[co  ][k,  k+1]
        float2 v10 = *(const float2*)(wp + 8 * KTOT);      // A[co+8][k,  k+1]
        float2 v01 = *(const float2*)(wp + 8);             // A[co  ][k+8,k+9]
        float2 v11 = *(const float2*)(wp + 8 * KTOT + 8);  // A[co+8][k+8,k+9]
        uint4 frag;
        frag.x = pack_h2(v00.x * 64.f, v00.y * 64.f);      // a0
        frag.y = pack_h2(v10.x * 64.f, v10.y * 64.f);      // a1
        frag.z = pack_h2(v01.x * 64.f, v01.y * 64.f);      // a2
        frag.w = pack_h2(v11.x * 64.f, v11.y * 64.f);      // a3
        *(uint4*)(g_afrag + (size_t)i * 16) = frag;
    }
}

// ---------------------------------------------------------------------------
// B producer split (unchanged from R12): LDG -> regs, then regs -> smem
// ---------------------------------------------------------------------------
__device__ __forceinline__ void load_b(
    int ch, const __half* xb, uint32_t koffs, int khalf, uint16_t (&bx)[16])
{
    const uint32_t kb4 = koffs + (uint32_t)(ch * 32 + khalf * 16) * 4;
    #pragma unroll
    for (int g = 0; g < 4; ++g) {
        uint32_t k0, k1, k2, k3;
        asm volatile("ld.shared.v4.b32 {%0,%1,%2,%3}, [%4];"
                     : "=r"(k0), "=r"(k1), "=r"(k2), "=r"(k3)
                     : "r"(kb4 + g * 16));
        bx[4*g+0] = ldg_b(xb + k0);
        bx[4*g+1] = ldg_b(xb + k1);
        bx[4*g+2] = ldg_b(xb + k2);
        bx[4*g+3] = ldg_b(xb + k3);
    }
}
__device__ __forceinline__ void store_b(
    uint32_t bufb, const uint16_t (&bx)[16], int prow, int khalf, uint32_t pswz)
{
    const uint32_t sB = bufb + (uint32_t)prow * 64;
    const uint32_t kobase = (uint32_t)khalf * 32;
    #pragma unroll
    for (int g = 0; g < 4; ++g) {
        uint32_t w0 = (uint32_t)bx[4*g+0] | ((uint32_t)bx[4*g+1] << 16);
        uint32_t w1 = (uint32_t)bx[4*g+2] | ((uint32_t)bx[4*g+3] << 16);
        sts64(sB + ((kobase + 8u * g) ^ pswz), w0, w1);
    }
}

// ---------------------------------------------------------------------------
// MMA consumer on one 32-k chunk. bufb = B stage base; A direct from global.
// aCh = this warp's fragment block for this chunk (+lane*64 already applied).
// ---------------------------------------------------------------------------
__device__ __forceinline__ void mma_chunk(
    uint32_t bufb, float (&acc)[4][4][4], const unsigned char* aCh,
    uint32_t bRowOff, uint32_t bKext, uint32_t bSwz)
{
    #pragma unroll
    for (int kb = 0; kb < 2; ++kb) {
        uint32_t a[16];
        ldg_a8(a,     aCh + kb * 2048);
        ldg_a8(a + 8, aCh + kb * 2048 + 32);

        const uint32_t kb2 = (uint32_t)kb * 32;
        const uint32_t bK = (kb2 + bKext) ^ bSwz;
        uint32_t bh[8];
        const uint32_t bAddr = bufb + bRowOff + bK;
        ldsm4(bAddr,        bh[0], bh[1], bh[2], bh[3]);
        ldsm4(bAddr + 1024, bh[4], bh[5], bh[6], bh[7]);

        #pragma unroll
        for (int am = 0; am < 4; ++am)
            #pragma unroll
            for (int an = 0; an < 4; ++an)
                mma_f16(acc[am][an], a + 4*am, bh[2*an], bh[2*an+1]);
    }
}

// ---------------------------------------------------------------------------
__global__ void __launch_bounds__(256, 2)
conv_mma_kernel(float* __restrict__ out)
{
    extern __shared__ char smem[];
    const uint32_t sb = smem_u32(smem);
    const int tid = threadIdx.x;
    const int bm = blockIdx.x;        // 0..3, fastest -> x gathers shared in L2
    const int bn = blockIdx.y;        // 0..728

    // im2col k -> x-offset table
    for (int k = tid; k < KTOT; k += 256) {
        int ci = k / 9, r9 = k - ci * 9;
        int kh = r9 / 3, kw = r9 - kh * 3;
        *(uint32_t*)(smem + OFF_KOFF + k * 4) = (uint32_t)(ci * 3136 + kh * 56 + kw);
    }

    // B producer invariants
    const int prow = tid >> 1, khalf = tid & 1;
    const int ng = bn * 128 + prow;
    const int bimg = ng / NPIMG;
    const int prem = ng - bimg * NPIMG;
    const int oh = prem / 54, ow = prem - oh * 54;
    const __half* xb = g_xh + (size_t)bimg * XIMG + oh * 56 + ow;
    const uint32_t pswz = (uint32_t)((prow >> 1) & 3) << 4;
    const uint32_t koffs = sb + OFF_KOFF;

    // MMA invariants: warp grid 2(m) x 4(n)
    const int lane = tid & 31, wid = tid >> 5;
    const int wm = wid & 1, wn = wid >> 1;
    // A fragment base: [mt][ch][wm][kb][lane][am][16B]
    const unsigned char* aCh = g_afrag
        + (size_t)bm * 72 * 8192 + (size_t)wm * 4096 + (size_t)lane * 64;
    const uint32_t bRowOff = (uint32_t)(wn * 32 + (lane & 7) + ((lane >> 4) << 3)) * 64;
    const uint32_t bKext   = (uint32_t)((lane >> 3) & 1) << 4;
    const uint32_t bSwz    = (uint32_t)(((lane & 7) >> 1) & 3) << 4;

    float acc[4][4][4];
    #pragma unroll
    for (int i = 0; i < 4; ++i)
        #pragma unroll
        for (int j = 0; j < 4; ++j)
            #pragma unroll
            for (int r = 0; r < 4; ++r) acc[i][j][r] = 0.0f;

    __syncthreads();                      // koff table ready

    // prologue: B stage 0
    {
        uint16_t bx0[16];
        load_b(0, xb, koffs, khalf, bx0);
        store_b(sb, bx0, prow, khalf, pswz);
    }
    __syncthreads();

    for (int ch = 0; ch < KCH; ++ch) {
        const uint32_t cur = sb + (uint32_t)(ch & 1) * STAGE_BYTES;
        const uint32_t nxt = sb + (uint32_t)((ch + 1) & 1) * STAGE_BYTES;
        const bool pre = (ch + 1 < KCH);

        uint16_t bx[16];
        if (pre)
            load_b(ch + 1, xb, koffs, khalf, bx);      // LDGs issue, no wait

        mma_chunk(cur, acc, aCh, bRowOff, bKext, bSwz);
        aCh += 8192;

        if (pre)
            store_b(nxt, bx, prow, khalf, pswz);       // LDGs landed during MMA
        __syncthreads();
    }

    // epilogue: scale by 1/64; streaming stores (evict-first)
    const float s = 0.015625f;
    const int lane4 = lane >> 2, lane2 = (lane & 3) * 2;
    #pragma unroll
    for (int an = 0; an < 4; ++an) {
        const int gn = bn * 128 + wn * 32 + an * 8 + lane2;
        const int b2 = gn / NPIMG;
        const int r2 = gn - b2 * NPIMG;
        float* op = out + (size_t)b2 * OUTIMG + r2;
        #pragma unroll
        for (int am = 0; am < 4; ++am) {
            const int co = bm * 128 + wm * 64 + am * 16 + lane4;
            stg_cs2(op + (size_t)co * NPIMG,
                    acc[am][an][0] * s, acc[am][an][1] * s);
            stg_cs2(op + (size_t)(co + 8) * NPIMG,
                    acc[am][an][2] * s, acc[am][an][3] * s);
        }
    }
}

// ---------------------------------------------------------------------------
extern "C" void kernel_launch(void* const* d_in, const int* in_sizes, int n_in,
                              void* d_out, int out_size)
{
    const float* x = (const float*)d_in[0];   // [32,256,56,56]
    const float* w = (const float*)d_in[1];   // [512,256,3,3]
    float* out = (float*)d_out;               // [32,512,54,54]

    cudaFuncSetAttribute(conv_mma_kernel,
                         cudaFuncAttributeMaxDynamicSharedMemorySize, SMEM_BYTES);

    prep_all<<<25664, 256>>>(x, w);           // fused pack_x + A fragments
    conv_mma_kernel<<<dim3(4, 729), 256, SMEM_BYTES>>>(out);
}

// round 14
// speedup vs baseline: 1.4454x; 1.4454x over previous
#include <cuda_runtime.h>
#include <cuda_fp16.h>
#include <cstdint>

// ============================================================================
// Single-term fp16 mma.sync implicit-GEMM conv, round 14.
// Same math as R12 champion (D = ah*bh, A=w*64 fp16, B=x fp16, ~2.9e-4).
// NEW B path: row-pair LDG.32 gathers (alignment via shifted x copy g_xh2),
// k-major swizzled B smem, ldmatrix.x4.trans consumption.
// B-LDG wavefronts/CTA/chunk: 256 -> ~96. A path identical to R12.
// ============================================================================

#define KTOT   2304
#define KCH    72            // 2304 / 32
#define NPIMG  2916
#define OUTIMG (512*NPIMG)
#define XIMG   (256*3136)
#define XN     (32*XIMG)     // 25690112 elements

#define A_TILE      8192     // A plane, 128 rows x 64B (swizzled, as R12)
#define STAGE_BYTES 16384    // A 8KB + B 8KB
#define OFF_B       8192
#define OFF_KOFF    32768                  // after 2 stages
#define SMEM_BYTES  (OFF_KOFF + KTOT*4)    // 41984

// A (scaled x64, fp16) in swizzled smem-tile layout: [mt(4)][ch(72)][8KB]
__device__ __align__(16) unsigned char g_asplit[4ull*72*8192];    // 2.4MB
// x as fp16, plus copy shifted by one element: g_xh2[j] = x_fp16[j+1]
__device__ __align__(16) __half g_xh [XN];                        // 51.4MB
__device__ __align__(16) __half g_xh2[XN];                        // 51.4MB

// ---------------------------------------------------------------------------
__device__ __forceinline__ uint32_t smem_u32(const void* p) {
    uint32_t a;
    asm("{ .reg .u64 t; cvta.to.shared.u64 t, %1; cvt.u32.u64 %0, t; }"
        : "=r"(a) : "l"(p));
    return a;
}
__device__ __forceinline__ void sts32(uint32_t addr, uint32_t v) {
    asm volatile("st.shared.b32 [%0], %1;" :: "r"(addr), "r"(v));
}
__device__ __forceinline__ void ldsm4(uint32_t a, uint32_t& r0, uint32_t& r1,
                                      uint32_t& r2, uint32_t& r3) {
    asm volatile("ldmatrix.sync.aligned.m8n8.x4.shared.b16 {%0,%1,%2,%3}, [%4];"
                 : "=r"(r0), "=r"(r1), "=r"(r2), "=r"(r3) : "r"(a));
}
__device__ __forceinline__ void ldsm4t(uint32_t a, uint32_t& r0, uint32_t& r1,
                                       uint32_t& r2, uint32_t& r3) {
    asm volatile("ldmatrix.sync.aligned.m8n8.x4.trans.shared.b16 {%0,%1,%2,%3}, [%4];"
                 : "=r"(r0), "=r"(r1), "=r"(r2), "=r"(r3) : "r"(a));
}
__device__ __forceinline__ void mma_f16(float* c, const uint32_t* a,
                                        uint32_t b0, uint32_t b1) {
    asm volatile(
        "mma.sync.aligned.m16n8k16.row.col.f32.f16.f16.f32 "
        "{%0,%1,%2,%3}, {%4,%5,%6,%7}, {%8,%9}, {%0,%1,%2,%3};"
        : "+f"(c[0]), "+f"(c[1]), "+f"(c[2]), "+f"(c[3])
        : "r"(a[0]), "r"(a[1]), "r"(a[2]), "r"(a[3]), "r"(b0), "r"(b1));
}
__device__ __forceinline__ void cpasync16(uint32_t dst, const void* src) {
    asm volatile("cp.async.cg.shared.global [%0], [%1], 16;"
                 :: "r"(dst), "l"(src) : "memory");
}
__device__ __forceinline__ void cp_commit() {
    asm volatile("cp.async.commit_group;" ::: "memory");
}
__device__ __forceinline__ void cp_wait0() {
    asm volatile("cp.async.wait_group 0;" ::: "memory");
}
__device__ __forceinline__ uint32_t ldg32(const void* p) {
    uint32_t v;
    asm volatile("ld.global.nc.u32 %0, [%1];" : "=r"(v) : "l"(p));
    return v;
}
__device__ __forceinline__ void stg_cs2(float* p, float a, float b) {
    asm volatile("st.global.cs.v2.f32 [%0], {%1, %2};"
                 :: "l"(p), "f"(a), "f"(b) : "memory");
}
__device__ __forceinline__ uint32_t pack_h2(float a, float b) {
    __half ha = __float2half_rn(a), hb = __float2half_rn(b);
    return (uint32_t)*(uint16_t*)&ha | ((uint32_t)*(uint16_t*)&hb << 16);
}

// ---------------------------------------------------------------------------
// fused prep: blocks [0,25088) pack x -> g_xh and shifted g_xh2;
//             [25088,25664) split A (identical to R12)
// ---------------------------------------------------------------------------
__global__ void prep_all(const float* __restrict__ x, const float* __restrict__ w) {
    const int b = blockIdx.x;
    if (b < 25088) {
        int i = b * 256 + threadIdx.x;               // 6422528 total
        float4 v = ((const float4*)x)[i];
        float nxt = (4 * i + 4 < XN) ? x[4 * i + 4] : 0.0f;
        ((uint2*)g_xh )[i] = make_uint2(pack_h2(v.x, v.y), pack_h2(v.z, v.w));
        ((uint2*)g_xh2)[i] = make_uint2(pack_h2(v.y, v.z), pack_h2(v.w, nxt));
    } else {
        int i = (b - 25088) * 256 + threadIdx.x;     // 147456 total
        int co = i / 288;
        int r  = i - co * 288;
        int ch = r >> 2, kq = r & 3;
        const float4* p = (const float4*)(w + (size_t)co * KTOT + ch * 32 + kq * 8);
        float4 v0 = p[0], v1 = p[1];
        uint32_t h0 = pack_h2(v0.x * 64.f, v0.y * 64.f);
        uint32_t h1 = pack_h2(v0.z * 64.f, v0.w * 64.f);
        uint32_t h2 = pack_h2(v1.x * 64.f, v1.y * 64.f);
        uint32_t h3 = pack_h2(v1.z * 64.f, v1.w * 64.f);
        int m = co & 127;
        size_t base = ((size_t)(co >> 7) * KCH + ch) * A_TILE
                    + m * 64 + (((uint32_t)kq * 16) ^ ((((uint32_t)m >> 1) & 3) << 4));
        *(uint4*)(g_asplit + base) = make_uint4(h0, h1, h2, h3);
    }
}

// ---------------------------------------------------------------------------
// B producer: thread -> rowpair p = tid&63 (rows 2p,2p+1), kslot = tid>>6.
// 8 x LDG.32 (two adjacent pixels, one k) -> 8 x STS.32 into k-major smem:
//   addr(k,n) = k*256 + ((2n) ^ ((k&7)<<4))
// ---------------------------------------------------------------------------
__device__ __forceinline__ void load_b(
    int ch, const __half* xb, const __half* xb2,
    uint32_t koffs, int kslot, uint32_t (&bx)[8])
{
    const uint32_t kb4 = koffs + (uint32_t)(ch * 32 + kslot * 8) * 4;
    uint32_t kk[8];
    asm volatile("ld.shared.v4.b32 {%0,%1,%2,%3}, [%4];"
                 : "=r"(kk[0]), "=r"(kk[1]), "=r"(kk[2]), "=r"(kk[3])
                 : "r"(kb4));
    asm volatile("ld.shared.v4.b32 {%0,%1,%2,%3}, [%4];"
                 : "=r"(kk[4]), "=r"(kk[5]), "=r"(kk[6]), "=r"(kk[7])
                 : "r"(kb4 + 16));
    #pragma unroll
    for (int g = 0; g < 8; ++g) {
        uint32_t ko = kk[g];
        const __half* base = (ko & 1) ? xb2 : xb;
        bx[g] = ldg32(base + (ko & ~1u));
    }
}
__device__ __forceinline__ void store_b(
    uint32_t bufb, const uint32_t (&bx)[8], int p, int kslot)
{
    const uint32_t sB = bufb + OFF_B + (uint32_t)kslot * 2048;
    const uint32_t np = (uint32_t)p * 4;            // 2n = 4p
    #pragma unroll
    for (int g = 0; g < 8; ++g)
        sts32(sB + (uint32_t)g * 256 + (np ^ ((uint32_t)g << 4)), bx[g]);
}

// ---------------------------------------------------------------------------
// MMA consumer on one 32-k chunk. buf: [A 0][B 8K]
// A: identical to R12 (n-major swizzled plane + ldsm4).
// B: k-major plane + ldsm4.trans; per-lane offsets precomputed (bOff1/2).
// ---------------------------------------------------------------------------
__device__ __forceinline__ void mma_chunk(
    uint32_t bufb, float (&acc)[4][4][4],
    uint32_t aRowOff, uint32_t aKext, uint32_t aSwz,
    uint32_t bOff1, uint32_t bOff2)
{
    #pragma unroll
    for (int kb = 0; kb < 2; ++kb) {
        const uint32_t aK = ((uint32_t)kb * 32 + aKext) ^ aSwz;
        const uint32_t bBase = bufb + OFF_B + (uint32_t)kb * 4096;

        uint32_t bh[8];
        ldsm4t(bBase + bOff1, bh[0], bh[1], bh[2], bh[3]);
        ldsm4t(bBase + bOff2, bh[4], bh[5], bh[6], bh[7]);

        uint32_t a[16];
        const uint32_t aAddr = bufb + aRowOff + aK;
        #pragma unroll
        for (int am = 0; am < 4; ++am)
            ldsm4(aAddr + am * 1024, a[4*am], a[4*am+1], a[4*am+2], a[4*am+3]);

        #pragma unroll
        for (int am = 0; am < 4; ++am)
            #pragma unroll
            for (int an = 0; an < 4; ++an)
                mma_f16(acc[am][an], a + 4*am, bh[2*an], bh[2*an+1]);
    }
}

// ---------------------------------------------------------------------------
__global__ void __launch_bounds__(256, 2)
conv_mma_kernel(float* __restrict__ out)
{
    extern __shared__ char smem[];
    const uint32_t sb = smem_u32(smem);
    const int tid = threadIdx.x;
    const int bm = blockIdx.x;        // 0..3, fastest -> x gathers shared in L2
    const int bn = blockIdx.y;        // 0..728

    // im2col k -> x-offset table (element offsets)
    for (int k = tid; k < KTOT; k += 256) {
        int ci = k / 9, r9 = k - ci * 9;
        int kh = r9 / 3, kw = r9 - kh * 3;
        *(uint32_t*)(smem + OFF_KOFF + k * 4) = (uint32_t)(ci * 3136 + kh * 56 + kw);
    }

    // A copy: 32B per thread per chunk (R12)
    const unsigned char* aBase = g_asplit + (size_t)bm * KCH * A_TILE
                               + (size_t)tid * 32;
    const uint32_t aOff = (uint32_t)tid * 32;

    // B producer invariants (rowpair mapping)
    const int p = tid & 63, kslot = tid >> 6;
    const int ng = bn * 128 + 2 * p;                 // even -> ow even
    const int bimg = ng / NPIMG;
    const int prem = ng - bimg * NPIMG;
    const int oh = prem / 54, ow = prem - oh * 54;
    const size_t idx0 = (size_t)bimg * XIMG + oh * 56 + ow;
    const __half* xb  = g_xh  + idx0;
    const __half* xb2 = g_xh2 + idx0;
    const uint32_t koffs = sb + OFF_KOFF;

    // MMA invariants: warp grid 2(m) x 4(n)
    const int lane = tid & 31, wid = tid >> 5;
    const int wm = wid & 1, wn = wid >> 1;
    const uint32_t aRowOff = (uint32_t)(wm * 64 + (lane & 15)) * 64;
    const uint32_t aKext   = (uint32_t)(lane >> 4) << 4;
    const uint32_t aSwz    = (uint32_t)(((lane & 15) >> 1) & 3) << 4;
    // B trans-ldsm per-lane row addresses (k-major layout)
    const int li = lane & 7, lgrp = lane >> 3;
    const int kLoc = li + ((lgrp & 1) << 3);
    const int nn1 = wn * 32 + ((lgrp >> 1) << 3);
    const uint32_t bOff1 = (uint32_t)kLoc * 256
                         + (((uint32_t)(2 * nn1))       ^ ((uint32_t)li << 4));
    const uint32_t bOff2 = (uint32_t)kLoc * 256
                         + (((uint32_t)(2 * (nn1 + 16))) ^ ((uint32_t)li << 4));

    float acc[4][4][4];
    #pragma unroll
    for (int i = 0; i < 4; ++i)
        #pragma unroll
        for (int j = 0; j < 4; ++j)
            #pragma unroll
            for (int r = 0; r < 4; ++r) acc[i][j][r] = 0.0f;

    __syncthreads();                      // koff table ready

    // prologue: stage 0
    cpasync16(sb + aOff,      aBase);
    cpasync16(sb + aOff + 16, aBase + 16);
    cp_commit();
    {
        uint32_t bx0[8];
        load_b(0, xb, xb2, koffs, kslot, bx0);
        store_b(sb, bx0, p, kslot);
    }
    cp_wait0();
    __syncthreads();

    for (int ch = 0; ch < KCH; ++ch) {
        const uint32_t cur = sb + (uint32_t)(ch & 1) * STAGE_BYTES;
        const uint32_t nxt = sb + (uint32_t)((ch + 1) & 1) * STAGE_BYTES;
        const bool pre = (ch + 1 < KCH);

        uint32_t bx[8];
        if (pre) {
            load_b(ch + 1, xb, xb2, koffs, kslot, bx);   // LDGs issue, no wait
            const unsigned char* aSrc = aBase + (size_t)(ch + 1) * A_TILE;
            cpasync16(nxt + aOff,      aSrc);
            cpasync16(nxt + aOff + 16, aSrc + 16);
            cp_commit();
        }

        mma_chunk(cur, acc, aRowOff, aKext, aSwz, bOff1, bOff2);

        if (pre)
            store_b(nxt, bx, p, kslot);                  // LDGs landed during MMA
        cp_wait0();
        __syncthreads();
    }

    // epilogue: scale by 1/64; streaming stores (evict-first)
    const float s = 0.015625f;
    const int lane4 = lane >> 2, lane2 = (lane & 3) * 2;
    #pragma unroll
    for (int an = 0; an < 4; ++an) {
        const int gn = bn * 128 + wn * 32 + an * 8 + lane2;
        const int b2 = gn / NPIMG;
        const int r2 = gn - b2 * NPIMG;
        float* op = out + (size_t)b2 * OUTIMG + r2;
        #pragma unroll
        for (int am = 0; am < 4; ++am) {
            const int co = bm * 128 + wm * 64 + am * 16 + lane4;
            stg_cs2(op + (size_t)co * NPIMG,
                    acc[am][an][0] * s, acc[am][an][1] * s);
            stg_cs2(op + (size_t)(co + 8) * NPIMG,
                    acc[am][an][2] * s, acc[am][an][3] * s);
        }
    }
}

// ---------------------------------------------------------------------------
extern "C" void kernel_launch(void* const* d_in, const int* in_sizes, int n_in,
                              void* d_out, int out_size)
{
    const float* x = (const float*)d_in[0];   // [32,256,56,56]
    const float* w = (const float*)d_in[1];   // [512,256,3,3]
    float* out = (float*)d_out;               // [32,512,54,54]

    cudaFuncSetAttribute(conv_mma_kernel,
                         cudaFuncAttributeMaxDynamicSharedMemorySize, SMEM_BYTES);

    prep_all<<<25664, 256>>>(x, w);           // pack x (+shifted copy) + split A
    conv_mma_kernel<<<dim3(4, 729), 256, SMEM_BYTES>>>(out);
}